// round 1
// baseline (speedup 1.0000x reference)
#include <cuda_runtime.h>

#define BB 4
#define NNPTS 40960
#define KK 16
#define HH 32
#define DD 64
#define PTOT (BB*NNPTS)

// scratch: f = relu(s2 * (W2 @ feature) + b2), layout [point][32] for 128B gathers
__device__ float g_f[(long)PTOT*HH];
__device__ int g_is64;

__device__ __forceinline__ unsigned long long pack2(float lo, float hi){
    unsigned long long r;
    asm("mov.b64 %0, {%1, %2};" : "=l"(r) : "f"(lo), "f"(hi));
    return r;
}
__device__ __forceinline__ void unpack2(unsigned long long v, float& lo, float& hi){
    asm("mov.b64 {%0, %1}, %2;" : "=f"(lo), "=f"(hi) : "l"(v));
}
__device__ __forceinline__ unsigned long long fma2(unsigned long long a, unsigned long long b, unsigned long long c){
    unsigned long long d;
    asm("fma.rn.f32x2 %0, %1, %2, %3;" : "=l"(d) : "l"(a), "l"(b), "l"(c));
    return d;
}

// ---------------------------------------------------------------------------
// idx dtype detector: int64 -> every odd 32-bit word of the buffer is 0.
__global__ void detect_idx_kernel(const int* __restrict__ neigh32){
    if (threadIdx.x == 0 && blockIdx.x == 0){
        int allzero = 1;
        for (int i = 0; i < 128; i++)
            if (neigh32[2*i + 1] != 0) { allzero = 0; break; }
        g_is64 = allzero;
    }
}

// ---------------------------------------------------------------------------
// Kernel A: f[p][h] = relu(s2[h]*(sum_d W2[h][d]*feature[b][d][n]) + b2[h])
__global__ void __launch_bounds__(256) kernelA(
    const float* __restrict__ feat, const float* __restrict__ W2,
    const float* __restrict__ g2, const float* __restrict__ b2)
{
    const int lane = threadIdx.x & 31;
    const int gwarp = (blockIdx.x*blockDim.x + threadIdx.x) >> 5;
    const int nwarps = (gridDim.x*blockDim.x) >> 5;
    const float inv = rsqrtf(1.0f + 1e-5f);
    const float s = g2[lane] * inv;
    const float bb = b2[lane];
    float w[DD];
    #pragma unroll
    for (int d = 0; d < DD; d++) w[d] = W2[lane*DD + d] * s;

    for (int p = gwarp; p < PTOT; p += nwarps){
        int b = p / NNPTS, n = p - b*NNPTS;
        const float* fp = feat + (long)b*DD*NNPTS + n;
        float acc = bb;
        #pragma unroll
        for (int d = 0; d < DD; d++) acc += w[d] * fp[(long)d*NNPTS];
        g_f[(long)p*HH + lane] = fmaxf(acc, 0.0f);
    }
}

// ---------------------------------------------------------------------------
// Kernel B: per point p (one warp): loop K neighbors -> W1 (pos enc), gather f,
// W3, relu, maxpool; epilogue W4 over [maxpool ; f_self]; staged coalesced write.
__global__ void __launch_bounds__(256) kernelB(
    const float* __restrict__ xyz, const int* __restrict__ neigh32,
    const float* __restrict__ W1, const float* __restrict__ g1, const float* __restrict__ b1,
    const float* __restrict__ W3, const float* __restrict__ g3, const float* __restrict__ b3,
    const float* __restrict__ W4, const float* __restrict__ g4, const float* __restrict__ b4,
    float* __restrict__ out)
{
    __shared__ unsigned long long sW4[32*64];      // [c_pair][o], scale folded
    __shared__ float sB4[64];
    __shared__ __align__(16) float sX[8][64];       // per-warp operand slab
    __shared__ float sOut[64][9];                   // [o][point-in-group], padded

    const int tid  = threadIdx.x;
    const int lane = tid & 31;
    const int wid  = tid >> 5;
    const float inv = rsqrtf(1.0f + 1e-5f);

    // load W4 (transposed pairs, scale folded) + b4 into smem
    for (int i = tid; i < 2048; i += 256){
        int c2 = i >> 6, o = i & 63;
        float2 wv = ((const float2*)W4)[o*32 + c2];
        float s4 = g4[o] * inv;
        sW4[i] = pack2(wv.x*s4, wv.y*s4);
    }
    if (tid < 64) sB4[tid] = b4[tid];

    // per-lane weight rows, scale folded, packed f32x2
    const float s1 = g1[lane]*inv, bb1 = b1[lane];
    const float s3 = g3[lane]*inv, bb3 = b3[lane];
    unsigned long long w1p[5];
    #pragma unroll
    for (int c = 0; c < 5; c++)
        w1p[c] = pack2(W1[lane*10 + 2*c]*s1, W1[lane*10 + 2*c + 1]*s1);
    unsigned long long w3p[32];
    #pragma unroll
    for (int c = 0; c < 32; c++)
        w3p[c] = pack2(W3[lane*64 + 2*c]*s3, W3[lane*64 + 2*c + 1]*s3);

    const int is64 = g_is64;
    __syncthreads();

    const int groups = PTOT / 8;   // 8 warps/block, one point per warp per group
    for (int grp = blockIdx.x; grp < groups; grp += gridDim.x){
        const int p = grp*8 + wid;
        const int b = p / NNPTS, n = p - b*NNPTS;
        const float* xb = xyz + (long)b*NNPTS*3;
        const float Px = xb[n*3+0], Py = xb[n*3+1], Pz = xb[n*3+2];
        const float fself = g_f[(long)p*HH + lane];

        const long ibase = (long)p*KK;
        int myidx = 0;
        if (lane < KK) myidx = is64 ? neigh32[2*(ibase + lane)] : neigh32[ibase + lane];

        float* xs = sX[wid];
        const unsigned long long* xp = (const unsigned long long*)xs;
        float maxv = -1e30f;

        // software-pipelined gathers (f row + neighbor xyz)
        int idx_c = __shfl_sync(0xffffffffu, myidx, 0);
        float fn_c = g_f[((long)b*NNPTS + idx_c)*HH + lane];
        float Qx_c = xb[idx_c*3+0], Qy_c = xb[idx_c*3+1], Qz_c = xb[idx_c*3+2];

        #pragma unroll 1
        for (int k = 0; k < KK; k++){
            int kn = (k+1 < KK) ? k+1 : k;
            int idx_n = __shfl_sync(0xffffffffu, myidx, kn);
            float fn_n = g_f[((long)b*NNPTS + idx_n)*HH + lane];
            float Qx_n = xb[idx_n*3+0], Qy_n = xb[idx_n*3+1], Qz_n = xb[idx_n*3+2];

            float rx = Px - Qx_c, ry = Py - Qy_c, rz = Pz - Qz_c;
            float dist = sqrtf(rx*rx + ry*ry + rz*rz);

            unsigned long long a1 = 0ull;
            a1 = fma2(w1p[0], pack2(dist, rx), a1);
            a1 = fma2(w1p[1], pack2(ry,  rz), a1);
            a1 = fma2(w1p[2], pack2(Px,  Py), a1);
            a1 = fma2(w1p[3], pack2(Pz,  Qx_c), a1);
            a1 = fma2(w1p[4], pack2(Qy_c, Qz_c), a1);
            float lo, hi; unpack2(a1, lo, hi);
            float h1 = fmaxf(lo + hi + bb1, 0.0f);

            xs[lane]      = fn_c;
            xs[32 + lane] = h1;
            __syncwarp();

            unsigned long long acc = 0ull;
            #pragma unroll
            for (int c = 0; c < 32; c++) acc = fma2(w3p[c], xp[c], acc);
            unpack2(acc, lo, hi);
            maxv = fmaxf(maxv, lo + hi + bb3);
            __syncwarp();

            fn_c = fn_n; idx_c = idx_n;
            Qx_c = Qx_n; Qy_c = Qy_n; Qz_c = Qz_n;
        }
        maxv = fmaxf(maxv, 0.0f);   // relu commutes with max

        // epilogue: out = relu(s4*(W4 @ [maxv ; fself]) + b4)
        xs[lane]      = maxv;
        xs[32 + lane] = fself;
        __syncwarp();
        unsigned long long a0 = 0ull, a1e = 0ull;
        #pragma unroll
        for (int c = 0; c < 32; c++){
            unsigned long long xv = xp[c];
            a0  = fma2(sW4[c*64 + lane],      xv, a0);
            a1e = fma2(sW4[c*64 + lane + 32], xv, a1e);
        }
        float l0, h0, l1, h1v;
        unpack2(a0, l0, h0); unpack2(a1e, l1, h1v);
        float o0 = fmaxf(sB4[lane]      + l0 + h0,  0.0f);
        float o1 = fmaxf(sB4[lane + 32] + l1 + h1v, 0.0f);
        __syncwarp();

        sOut[lane][wid]      = o0;
        sOut[lane + 32][wid] = o1;
        __syncthreads();
        for (int i = tid; i < 512; i += 256){
            int o = i >> 3, j = i & 7;
            int pp = grp*8 + j;
            int b2_ = pp / NNPTS, n2_ = pp - b2_*NNPTS;
            out[((long)b2_*DD + o)*NNPTS + n2_] = sOut[o][j];
        }
        __syncthreads();
    }
}

// ---------------------------------------------------------------------------
extern "C" void kernel_launch(void* const* d_in, const int* in_sizes, int n_in,
                              void* d_out, int out_size)
{
    const float *feature=0, *xyzp=0, *W1=0, *W2=0, *W3=0, *W4=0;
    const void* neigh=0;
    const float* s32[6] = {0,0,0,0,0,0};   // g1,b1,g2,b2,g3,b3 (encounter order)
    const float* s64[2] = {0,0};           // g4,b4
    int n2048 = 0, c32 = 0, c64 = 0;
    for (int i = 0; i < n_in; i++){
        int sz = in_sizes[i];
        const float* p = (const float*)d_in[i];
        if      (sz == 10485760) feature = p;
        else if (sz == 491520)   xyzp = p;
        else if (sz == 2621440)  neigh = d_in[i];
        else if (sz == 320)      W1 = p;
        else if (sz == 2048)     { if (n2048++ == 0) W2 = p; else W3 = p; }
        else if (sz == 4096)     W4 = p;
        else if (sz == 32)       { if (c32 < 6) s32[c32++] = p; }
        else if (sz == 64)       { if (c64 < 2) s64[c64++] = p; }
    }

    detect_idx_kernel<<<1, 1>>>((const int*)neigh);
    kernelA<<<1184, 256>>>(feature, W2, s32[2], s32[3]);
    kernelB<<<592, 256>>>(xyzp, (const int*)neigh,
                          W1, s32[0], s32[1],
                          W3, s32[4], s32[5],
                          W4, s64[0], s64[1],
                          (float*)d_out);
}